// round 6
// baseline (speedup 1.0000x reference)
#include <cuda_runtime.h>
#include <cuda_bf16.h>
#include <cstdint>

// Problem constants
#define BB 256
#define TT 256
#define CC 1024
#define LL 64
#define SS 129          // 2L+1
#define SP 132          // padded stride (16B-aligned rows)
#define NEGV (-1e30f)
#define EPSV (1e-7f)

// Scratch: emit log-probs, (B*T, SP) fp32  ~34.6 MB
__device__ float g_emit[(size_t)BB * TT * SP];

// ---------------------------------------------------------------------------
// Kernel A: per (b,t) row — compute lse = log(sum(y_pred)+C*eps), gather the
// 129 extended-label log-probs. One block per (b,t), 256 threads.
// log_softmax(log(p+eps)) = log(p+eps) - log(sum(p) + C*eps)
// ---------------------------------------------------------------------------
__global__ void __launch_bounds__(256) emit_kernel(
    const float* __restrict__ y_pred,
    const int* __restrict__ y_true)
{
    int bt = blockIdx.x;          // b*T + t
    int b  = bt >> 8;             // T = 256
    int tid = threadIdx.x;

    __shared__ float srow[CC];
    __shared__ float partial[8];
    __shared__ float s_lse;

    const float4* row = reinterpret_cast<const float4*>(y_pred + (size_t)bt * CC);
    float4 v = row[tid];
    reinterpret_cast<float4*>(srow)[tid] = v;
    float s = (v.x + v.y) + (v.z + v.w);

    // warp reduce
    #pragma unroll
    for (int o = 16; o > 0; o >>= 1) s += __shfl_xor_sync(0xffffffffu, s, o);
    if ((tid & 31) == 0) partial[tid >> 5] = s;
    __syncthreads();
    if (tid < 32) {
        float ps = (tid < 8) ? partial[tid] : 0.0f;
        #pragma unroll
        for (int o = 4; o > 0; o >>= 1) ps += __shfl_xor_sync(0xffffffffu, ps, o);
        if (tid == 0) s_lse = __logf(ps + (float)CC * EPSV);
    }
    __syncthreads();

    if (tid < SS) {
        int label = (tid & 1) ? y_true[b * LL + (tid >> 1)] : (CC - 1);
        g_emit[(size_t)bt * SP + tid] = __logf(srow[label] + EPSV) - s_lse;
    }
}

// ---------------------------------------------------------------------------
// Kernel B: CTC forward recursion. One block per batch, 160 threads
// (129 active states), double-buffered alpha in shared, 1 barrier per step.
// ---------------------------------------------------------------------------
__global__ void __launch_bounds__(160) ctc_kernel(
    const int* __restrict__ y_true,
    float* __restrict__ out)
{
    int b   = blockIdx.x;
    int tid = threadIdx.x;
    bool active = (tid < SS);

    // alpha buffers, indices shifted by +2 so [0],[1] are permanent NEG pads.
    __shared__ float alpha[2][SS + 2 + 33];   // pad tail so inactive lanes read in-bounds

    const float* em = g_emit + (size_t)b * TT * SP;

    // skip_ok: only odd states, label index >=1, label != blank, label != prev label
    bool skip = false;
    if (active && (tid & 1)) {
        int idx = tid >> 1;
        int lab = y_true[b * LL + idx];
        if (idx >= 1 && lab != (CC - 1) && lab != y_true[b * LL + idx - 1])
            skip = true;
    }

    // init t=0: alpha0 = emit[0,s] for s<2, else NEG
    if (tid < 2) { alpha[0][tid] = NEGV; alpha[1][tid] = NEGV; }
    if (active) {
        float a0 = (tid < 2) ? em[tid] : NEGV;
        alpha[0][tid + 2] = a0;
    } else {
        alpha[0][tid + 2] = NEGV;
        alpha[1][tid + 2] = NEGV;
    }

    // prefetch emit for t=1
    float emit_next = active ? __ldg(em + SP + tid) : 0.0f;
    __syncthreads();

    int cur = 0;
    for (int t = 1; t < TT; t++) {
        float e = emit_next;
        if (t + 1 < TT && active)
            emit_next = __ldg(em + (size_t)(t + 1) * SP + tid);

        float a1 = alpha[cur][tid + 2];
        float a2 = alpha[cur][tid + 1];
        float a3 = skip ? alpha[cur][tid] : NEGV;
        float m  = fmaxf(a1, fmaxf(a2, a3));
        float anew = m + __logf(__expf(a1 - m) + __expf(a2 - m) + __expf(a3 - m)) + e;

        if (active) alpha[cur ^ 1][tid + 2] = anew;
        __syncthreads();
        cur ^= 1;
    }

    if (tid == 0) {
        float t1 = alpha[cur][SS - 2 + 2];
        float t2 = alpha[cur][SS - 1 + 2];
        float m  = fmaxf(t1, t2);
        float ll = m + __logf(__expf(t1 - m) + __expf(t2 - m));
        out[b] = -ll;
    }
}

// ---------------------------------------------------------------------------
extern "C" void kernel_launch(void* const* d_in, const int* in_sizes, int n_in,
                              void* d_out, int out_size)
{
    // Identify inputs by element count: y_true = B*L = 16384 (int32),
    // y_pred = B*T*C = 67108864 (float32).
    const int*   y_true = nullptr;
    const float* y_pred = nullptr;
    for (int i = 0; i < n_in; i++) {
        if (in_sizes[i] == BB * LL)           y_true = (const int*)d_in[i];
        else if (in_sizes[i] == BB * TT * CC) y_pred = (const float*)d_in[i];
    }
    float* out = (float*)d_out;

    emit_kernel<<<BB * TT, 256>>>(y_pred, y_true);
    ctc_kernel<<<BB, 160>>>(y_true, out);
}